// round 4
// baseline (speedup 1.0000x reference)
#include <cuda_runtime.h>

// Problem constants
#define NN   50000
#define NE   1600000
#define TT   (NE + NN)       // edges + self loops
#define INCH 256
#define HID  64
#define LAT  32
#define GATH 32
#define OUTC 256
#define NPART 196            // ceil(NN/256)

// ---------------------------------------------------------------------------
// Device scratch (static only)
// ---------------------------------------------------------------------------
__device__ __align__(128) float g_H1[NN * 64];
__device__ __align__(128) float g_H2[NN * 64];
__device__ __align__(128) float g_H3[NN * 32];
__device__ __align__(128) float g_hg[NN * 32];
__device__ __align__(128) float g_gh[NN * 32];
__device__ __align__(128) float g_hf[NN * 32];
__device__ __align__(128) float g_s[NN];
__device__ __align__(128) float g_d[NN];
__device__ __align__(128) int   g_deg[NN];
__device__ __align__(128) int   g_rowoff[NN];
__device__ __align__(128) int   g_cursor[NN];
__device__ __align__(128) int   g_csr[TT];
__device__ int   g_partial[256];
// NOTE: zero at module load; every STATS accumulation is followed by bnprep_k
// which re-zeroes — invariant holds across calls with no init kernel needed.
__device__ float g_colsum[64], g_colsq[64];
__device__ float g_scale[64], g_shift[64];

// ---------------------------------------------------------------------------
// Streams/events for parallel-branch graph capture. Created at module load
// (static init), BEFORE the harness's memory checkpoints — kernel_launch
// itself performs no resource creation.
// ---------------------------------------------------------------------------
struct GpuCtx {
    cudaStream_t s1, s2;
    cudaEvent_t  e0, e1, e2;
    GpuCtx() {
        cudaStreamCreateWithFlags(&s1, cudaStreamNonBlocking);
        cudaStreamCreateWithFlags(&s2, cudaStreamNonBlocking);
        cudaEventCreateWithFlags(&e0, cudaEventDisableTiming);
        cudaEventCreateWithFlags(&e1, cudaEventDisableTiming);
        cudaEventCreateWithFlags(&e2, cudaEventDisableTiming);
    }
};
static GpuCtx g_ctx;

// ---------------------------------------------------------------------------
// f32x2 packed-FMA helpers (sm_103a FFMA2 path — PTX only)
// ---------------------------------------------------------------------------
typedef unsigned long long u64;
__device__ __forceinline__ u64 pack2(float a, float b) {
    u64 r; asm("mov.b64 %0,{%1,%2};" : "=l"(r) : "f"(a), "f"(b)); return r;
}
__device__ __forceinline__ void fma2(u64& d, u64 a, u64 b) {
    asm("fma.rn.f32x2 %0, %1, %2, %0;" : "+l"(d) : "l"(a), "l"(b));
}
__device__ __forceinline__ void unpk2(u64 v, float& x, float& y) {
    asm("mov.b64 {%0,%1},%2;" : "=f"(x), "=f"(y) : "l"(v));
}

// ---------------------------------------------------------------------------
// Fused tiled GEMM:  C[N,F] = act(load(A)[N,K] @ W[K,F] + bias)
//   BNIN : A-load applies y = relu(A*scale[k]+shift[k])
//   BLEND: A-load then v = 0.5*(v + A2)
//   STATS: epilogue accumulates column sum/sumsq of C (post-bias)
//   SD   : epilogue computes per-row dots with as_/ad_ -> g_s/g_d
// Tile 64 rows x FT cols, K chunks of 32, 256 threads.
// ---------------------------------------------------------------------------
template<int FT, bool RELU, bool BLEND, bool BNIN, bool STATS, bool SD>
__global__ __launch_bounds__(256) void gemm_k(
    const float* __restrict__ A, const float* __restrict__ A2,
    const float* __restrict__ W, const float* __restrict__ bias,
    const float* __restrict__ as_, const float* __restrict__ ad_,
    float* __restrict__ C, int N, int K, int F)
{
    __shared__ __align__(16) float Ash[64][33];
    __shared__ __align__(16) float Wsh[32][FT];
    __shared__ float s_sum[FT], s_sq[FT];

    const int tid   = threadIdx.x;
    const int rbase = blockIdx.x * 64;
    const int cbase = blockIdx.y * FT;
    constexpr int CPT = FT / 4;
    constexpr int CP2 = CPT / 2;
    const int row = tid >> 2, cg = tid & 3;

    if (STATS && tid < FT) { s_sum[tid] = 0.f; s_sq[tid] = 0.f; }

    u64 acc2[CP2];
#pragma unroll
    for (int j = 0; j < CP2; j++) acc2[j] = 0ull;

    for (int k0 = 0; k0 < K; k0 += 32) {
#pragma unroll
        for (int p = 0; p < 8; p++) {
            int idx = tid + p * 256;
            int r = idx >> 5, c = idx & 31;
            int gr = rbase + r;
            float v = 0.f;
            if (gr < N) {
                v = A[(long)gr * K + k0 + c];
                if (BNIN) { int kc = k0 + c; v = fmaxf(fmaf(v, g_scale[kc], g_shift[kc]), 0.f); }
                if (BLEND) v = 0.5f * (v + A2[(long)gr * K + k0 + c]);
            }
            Ash[r][c] = v;
        }
#pragma unroll
        for (int idx = tid; idx < 32 * FT; idx += 256) {
            int r = idx / FT, c = idx % FT;
            Wsh[r][c] = W[(long)(k0 + r) * F + cbase + c];
        }
        __syncthreads();
#pragma unroll
        for (int kk = 0; kk < 32; kk++) {
            float a = Ash[row][kk];
            u64 a2 = pack2(a, a);
            const u64* wr = reinterpret_cast<const u64*>(&Wsh[kk][cg * CPT]);
#pragma unroll
            for (int j = 0; j < CP2; j++) fma2(acc2[j], a2, wr[j]);
        }
        __syncthreads();
    }

    float av[CPT];
#pragma unroll
    for (int j = 0; j < CP2; j++) unpk2(acc2[j], av[2 * j], av[2 * j + 1]);

    int gr = rbase + row;
    bool valid = gr < N;

    if (SD) {
        float sp = 0.f, dp = 0.f;
#pragma unroll
        for (int j = 0; j < CPT; j++) {
            float h = av[j];
            sp = fmaf(h, as_[cg * CPT + j], sp);
            dp = fmaf(h, ad_[cg * CPT + j], dp);
        }
        sp += __shfl_xor_sync(0xffffffffu, sp, 1);
        dp += __shfl_xor_sync(0xffffffffu, dp, 1);
        sp += __shfl_xor_sync(0xffffffffu, sp, 2);
        dp += __shfl_xor_sync(0xffffffffu, dp, 2);
        if (cg == 0 && valid) { g_s[gr] = sp; g_d[gr] = dp; }
    }

#pragma unroll
    for (int j = 0; j < CPT; j++) {
        int c = cbase + cg * CPT + j;
        float v = av[j];
        if (bias) v += bias[c];
        if (STATS) {
            float sv = valid ? v : 0.f;
            float sq = sv * sv;
#pragma unroll
            for (int o = 16; o >= 4; o >>= 1) {
                sv += __shfl_down_sync(0xffffffffu, sv, o);
                sq += __shfl_down_sync(0xffffffffu, sq, o);
            }
            if ((tid & 31) < 4) {
                atomicAdd(&s_sum[cg * CPT + j], sv);
                atomicAdd(&s_sq[cg * CPT + j], sq);
            }
        }
        if (RELU) v = fmaxf(v, 0.f);
        if (valid) C[(long)gr * F + c] = v;
    }

    if (STATS) {
        __syncthreads();
        if (tid < FT) {
            atomicAdd(&g_colsum[tid], s_sum[tid]);
            atomicAdd(&g_colsq[tid], s_sq[tid]);
        }
    }
}

// ---------------------------------------------------------------------------
// BatchNorm prep: scale/shift from accumulated stats; self-zeroes stats.
// ---------------------------------------------------------------------------
__global__ void bnprep_k(const float* __restrict__ g, const float* __restrict__ be, int Cc) {
    int c = threadIdx.x;
    float cs = (c < 64) ? g_colsum[c] : 0.f;
    float cq = (c < 64) ? g_colsq[c] : 0.f;
    if (c < Cc) {
        float invN = 1.0f / (float)NN;
        float m = cs * invN;
        float v = cq * invN - m * m;
        float sc = g[c] * rsqrtf(v + 1e-5f);
        g_scale[c] = sc;
        g_shift[c] = fmaf(-m, sc, be[c]);
    }
    if (c < 64) { g_colsum[c] = 0.f; g_colsq[c] = 0.f; }
}

// ---------------------------------------------------------------------------
// CSR build
// ---------------------------------------------------------------------------
__global__ void init_k() {
    int i = blockIdx.x * 256 + threadIdx.x;
    if (i < NN) g_deg[i] = 0;
}

__global__ __launch_bounds__(256) void hist_k(const int* __restrict__ ei) {
    int t = blockIdx.x * 256 + threadIdx.x;
    if (t >= TT) return;
    int dst = (t < NE) ? ei[NE + t] : (t - NE);
    atomicAdd(&g_deg[dst], 1);
}

__global__ __launch_bounds__(256) void scan1_k() {
    __shared__ int ws[9];
    int t = threadIdx.x, b = blockIdx.x;
    int i = b * 256 + t;
    int v = (i < NN) ? g_deg[i] : 0;
    int lane = t & 31, wid = t >> 5;
    int x = v;
#pragma unroll
    for (int o = 1; o < 32; o <<= 1) {
        int y = __shfl_up_sync(0xffffffffu, x, o);
        if (lane >= o) x += y;
    }
    if (lane == 31) ws[wid] = x;
    __syncthreads();
    if (t == 0) {
        int s = 0;
        for (int w = 0; w < 8; w++) { int tmp = ws[w]; ws[w] = s; s += tmp; }
        ws[8] = s;
    }
    __syncthreads();
    int excl = x - v + ws[wid];
    if (i < NN) g_rowoff[i] = excl;
    if (t == 0) g_partial[b] = ws[8];
}

__global__ __launch_bounds__(256) void scan2_k() {
    __shared__ int ws[9];
    int t = threadIdx.x;
    int v = (t < NPART) ? g_partial[t] : 0;
    int lane = t & 31, wid = t >> 5;
    int x = v;
#pragma unroll
    for (int o = 1; o < 32; o <<= 1) {
        int y = __shfl_up_sync(0xffffffffu, x, o);
        if (lane >= o) x += y;
    }
    if (lane == 31) ws[wid] = x;
    __syncthreads();
    if (t == 0) {
        int s = 0;
        for (int w = 0; w < 8; w++) { int tmp = ws[w]; ws[w] = s; s += tmp; }
        ws[8] = s;
    }
    __syncthreads();
    if (t < NPART) g_partial[t] = x - v + ws[wid];
}

__global__ void scan3_k() {
    int i = blockIdx.x * 256 + threadIdx.x;
    if (i < NN) {
        int off = g_rowoff[i] + g_partial[i >> 8];
        g_rowoff[i] = off;
        g_cursor[i] = off;
    }
}

__global__ __launch_bounds__(256) void scatter_k(const int* __restrict__ ei) {
    int t = blockIdx.x * 256 + threadIdx.x;
    if (t >= TT) return;
    int src, dst;
    if (t < NE) { src = ei[t]; dst = ei[NE + t]; }
    else        { src = dst = t - NE; }
    int p = atomicAdd(&g_cursor[dst], 1);
    g_csr[p] = src;
}

// ---------------------------------------------------------------------------
// GAT softmax-aggregate: warp per dst node, no atomics; exact-trip remainder.
// ---------------------------------------------------------------------------
__global__ __launch_bounds__(256) void agg_k(const float* __restrict__ Hg,
                                             const float* __restrict__ bias,
                                             float* __restrict__ outR) {
    int w = (blockIdx.x * 256 + threadIdx.x) >> 5;
    int lane = threadIdx.x & 31;
    if (w >= NN) return;
    int beg = g_rowoff[w];
    int n   = g_deg[w];
    float dd = g_d[w];
    float acc = 0.f, den = 0.f;
    int p0 = 0;
    for (; p0 + 32 <= n; p0 += 32) {
        int src = g_csr[beg + p0 + lane];
        float e = g_s[src] + dd;
        e = e > 0.f ? e : 0.2f * e;
        float ex = __expf(e);
#pragma unroll
        for (int j = 0; j < 32; j++) {
            float exj = __shfl_sync(0xffffffffu, ex, j);
            int   sj  = __shfl_sync(0xffffffffu, src, j);
            acc = fmaf(exj, Hg[sj * 32 + lane], acc);
            den += exj;
        }
    }
    int rem = n - p0;
    if (rem) {
        int src = 0; float ex = 0.f;
        if (lane < rem) {
            src = g_csr[beg + p0 + lane];
            float e = g_s[src] + dd;
            e = e > 0.f ? e : 0.2f * e;
            ex = __expf(e);
        }
        for (int j = 0; j < rem; j++) {
            float exj = __shfl_sync(0xffffffffu, ex, j);
            int   sj  = __shfl_sync(0xffffffffu, src, j);
            acc = fmaf(exj, Hg[sj * 32 + lane], acc);
            den += exj;
        }
    }
    outR[w * 32 + lane] = fmaxf(acc / den + bias[lane], 0.f);
}

// ---------------------------------------------------------------------------
// Orchestration: 3-way parallel branches (CSR ∥ MLP ∥ GAT-g1), join for agg.
// ---------------------------------------------------------------------------
extern "C" void kernel_launch(void* const* d_in, const int* in_sizes, int n_in,
                              void* d_out, int out_size)
{
    const float* x     = (const float*)d_in[0];
    const int*   ei    = (const int*)  d_in[1];
    const float* W_g1  = (const float*)d_in[2];
    const float* as_g1 = (const float*)d_in[3];
    const float* ad_g1 = (const float*)d_in[4];
    const float* b_g1  = (const float*)d_in[5];
    const float* W_g2  = (const float*)d_in[6];
    const float* as_g2 = (const float*)d_in[7];
    const float* ad_g2 = (const float*)d_in[8];
    const float* b_g2  = (const float*)d_in[9];
    const float* W_gf  = (const float*)d_in[10];
    const float* b_gf  = (const float*)d_in[11];
    const float* W_m1  = (const float*)d_in[12];
    const float* b_m1  = (const float*)d_in[13];
    const float* g_m1  = (const float*)d_in[14];
    const float* be_m1 = (const float*)d_in[15];
    const float* W_m2  = (const float*)d_in[16];
    const float* b_m2  = (const float*)d_in[17];
    const float* g_m2  = (const float*)d_in[18];
    const float* be_m2 = (const float*)d_in[19];
    const float* W_m3  = (const float*)d_in[20];
    const float* b_m3  = (const float*)d_in[21];
    const float* g_m3  = (const float*)d_in[22];
    const float* be_m3 = (const float*)d_in[23];
    const float* W_f   = (const float*)d_in[24];
    const float* b_f   = (const float*)d_in[25];
    float* out = (float*)d_out;

    float *H1, *H2, *H3, *hg, *gh, *hf;
    cudaGetSymbolAddress((void**)&H1, g_H1);
    cudaGetSymbolAddress((void**)&H2, g_H2);
    cudaGetSymbolAddress((void**)&H3, g_H3);
    cudaGetSymbolAddress((void**)&hg, g_hg);
    cudaGetSymbolAddress((void**)&gh, g_gh);
    cudaGetSymbolAddress((void**)&hf, g_hf);

    const int GROWS = (NN + 63) / 64;
    const int EBLK  = (TT + 255) / 256;
    const int NBLK  = (NN + 255) / 256;
    const int ABLK  = (NN * 32 + 255) / 256;

    cudaStream_t s1 = g_ctx.s1, s2 = g_ctx.s2;

    // Fork point: branches depend on nothing before this.
    cudaEventRecord(g_ctx.e0, 0);

    // ---- Branch 0 (capture stream): CSR build part 1 ----
    init_k<<<NBLK, 256>>>();                                        // #1
    hist_k<<<EBLK, 256>>>(ei);                                      // #2
    scan1_k<<<NPART, 256>>>();                                      // #3

    // ---- Branch 1 (s1): MLP chain ----
    cudaStreamWaitEvent(s1, g_ctx.e0, 0);
    gemm_k<64, false, false, false, true, false><<<dim3(GROWS, 1), 256, 0, s1>>>(
        x, nullptr, W_m1, b_m1, nullptr, nullptr, H1, NN, INCH, HID);   // #4 <- profiled
    bnprep_k<<<1, 64, 0, s1>>>(g_m1, be_m1, 64);                        // #5
    gemm_k<64, false, false, true, true, false><<<dim3(GROWS, 1), 256, 0, s1>>>(
        H1, nullptr, W_m2, b_m2, nullptr, nullptr, H2, NN, HID, HID);
    bnprep_k<<<1, 64, 0, s1>>>(g_m2, be_m2, 64);
    gemm_k<32, false, false, true, true, false><<<dim3(GROWS, 1), 256, 0, s1>>>(
        H2, nullptr, W_m3, b_m3, nullptr, nullptr, H3, NN, HID, LAT);
    bnprep_k<<<1, 64, 0, s1>>>(g_m3, be_m3, 32);
    cudaEventRecord(g_ctx.e1, s1);

    // ---- Branch 2 (s2): GAT layer-1 GEMM ----
    cudaStreamWaitEvent(s2, g_ctx.e0, 0);
    gemm_k<32, false, false, false, false, true><<<dim3(GROWS, 1), 256, 0, s2>>>(
        x, nullptr, W_g1, nullptr, as_g1, ad_g1, hg, NN, INCH, GATH);
    cudaEventRecord(g_ctx.e2, s2);

    // ---- Branch 0 continues: CSR build part 2 ----
    scan2_k<<<1, 256>>>();
    scan3_k<<<NBLK, 256>>>();
    scatter_k<<<EBLK, 256>>>(ei);

    // ---- Join GAT-g1, run GAT chain on capture stream ----
    cudaStreamWaitEvent(0, g_ctx.e2, 0);
    agg_k<<<ABLK, 256>>>(hg, b_g1, gh);
    gemm_k<32, false, false, false, false, true><<<dim3(GROWS, 1), 256>>>(
        gh, nullptr, W_g2, nullptr, as_g2, ad_g2, hg, NN, GATH, GATH);
    agg_k<<<ABLK, 256>>>(hg, b_g2, gh);
    gemm_k<32, false, false, false, false, false><<<dim3(GROWS, 1), 256>>>(
        gh, nullptr, W_gf, b_gf, nullptr, nullptr, hf, NN, GATH, LAT);

    // ---- Join MLP, final blended GEMM ----
    cudaStreamWaitEvent(0, g_ctx.e1, 0);
    gemm_k<128, true, true, true, false, false><<<dim3(GROWS, 2), 256>>>(
        H3, hf, W_f, b_f, nullptr, nullptr, out, NN, LAT, OUTC);
}

// round 5
// speedup vs baseline: 2.6363x; 2.6363x over previous
#include <cuda_runtime.h>

// Problem constants
#define NN   50000
#define NE   1600000
#define TT   (NE + NN)       // edges + self loops
#define INCH 256
#define HID  64
#define LAT  32
#define GATH 32
#define OUTC 256
#define NPART 196            // ceil(NN/256)

// ---------------------------------------------------------------------------
// Device scratch (static only)
// ---------------------------------------------------------------------------
__device__ __align__(128) float g_H1[NN * 64];
__device__ __align__(128) float g_H2[NN * 64];
__device__ __align__(128) float g_H3[NN * 32];
__device__ __align__(128) float g_hg[NN * 32];
__device__ __align__(128) float g_gh[NN * 32];
__device__ __align__(128) float g_hf[NN * 32];
__device__ __align__(128) float g_s[NN];
__device__ __align__(128) float g_d[NN];
__device__ __align__(128) int   g_deg[NN];
__device__ __align__(128) int   g_rowoff[NN];
__device__ __align__(128) int   g_cursor[NN];
__device__ __align__(128) int   g_csr[TT];
__device__ int   g_partial[256];
// zero at module load; bnprep_k re-zeroes after each use -> invariant holds.
__device__ float g_colsum[64], g_colsq[64];
__device__ float g_scale[64], g_shift[64];

// ---------------------------------------------------------------------------
// Streams/events created at module load (before harness mem checkpoints).
// ---------------------------------------------------------------------------
struct GpuCtx {
    cudaStream_t s1, s2;
    cudaEvent_t  e0, e1, e2;
    GpuCtx() {
        cudaStreamCreateWithFlags(&s1, cudaStreamNonBlocking);
        cudaStreamCreateWithFlags(&s2, cudaStreamNonBlocking);
        cudaEventCreateWithFlags(&e0, cudaEventDisableTiming);
        cudaEventCreateWithFlags(&e1, cudaEventDisableTiming);
        cudaEventCreateWithFlags(&e2, cudaEventDisableTiming);
    }
};
static GpuCtx g_ctx;

// ---------------------------------------------------------------------------
// f32x2 packed-FMA helpers (sm_103a FFMA2 — PTX only)
// ---------------------------------------------------------------------------
typedef unsigned long long u64;
__device__ __forceinline__ u64 pack2(float a, float b) {
    u64 r; asm("mov.b64 %0,{%1,%2};" : "=l"(r) : "f"(a), "f"(b)); return r;
}
__device__ __forceinline__ void fma2(u64& d, u64 a, u64 b) {
    asm("fma.rn.f32x2 %0, %1, %2, %0;" : "+l"(d) : "l"(a), "l"(b));
}
__device__ __forceinline__ void unpk2(u64 v, float& x, float& y) {
    asm("mov.b64 {%0,%1},%2;" : "=f"(x), "=f"(y) : "l"(v));
}

// ---------------------------------------------------------------------------
// Register-blocked fused GEMM:  C[N,F] = act(load(A)[N,K] @ W[K,F] + bias)
// Block tile: 128 rows x FT cols. 256 threads. Micro-tile 4 rows x CPT cols.
//   rg = tid>>3 (0..31) -> rows rg*4..rg*4+3 ; cg = tid&7 -> cols cg*CPT..
//   Inner k-iter: 4 LDS.32 (A) + LDS.128s (W) -> 4*CP2 fma2.
// Flags: BNIN (bn+relu on A load), BLEND (0.5*(A+A2)), STATS (col sum/sq of
// C post-bias), SD (per-row dots vs as_/ad_ -> g_s/g_d; requires FT==32).
// ---------------------------------------------------------------------------
template<int FT, bool RELU, bool BLEND, bool BNIN, bool STATS, bool SD>
__global__ __launch_bounds__(256) void gemm_k(
    const float* __restrict__ A, const float* __restrict__ A2,
    const float* __restrict__ W, const float* __restrict__ bias,
    const float* __restrict__ as_, const float* __restrict__ ad_,
    float* __restrict__ C, int N, int K, int F)
{
    constexpr int CPT = (FT >= 64) ? 8 : 4;   // cols per thread
    constexpr int CP2 = CPT / 2;              // u64 accumulators per row
    static_assert(FT / CPT == 8, "need 8 col groups");

    __shared__ __align__(16) float Ash[128][33];
    __shared__ __align__(16) float Wsh[32][FT];
    __shared__ float s_sum[FT], s_sq[FT];

    const int tid   = threadIdx.x;
    const int rbase = blockIdx.x * 128;
    const int cbase = blockIdx.y * FT;
    const int rg = tid >> 3, cg = tid & 7;
    const int r0 = rg * 4, c0 = cg * CPT;

    if (STATS && tid < FT) { s_sum[tid] = 0.f; s_sq[tid] = 0.f; }

    u64 acc[4][CP2];
#pragma unroll
    for (int i = 0; i < 4; i++)
#pragma unroll
        for (int j = 0; j < CP2; j++) acc[i][j] = 0ull;

    for (int k0 = 0; k0 < K; k0 += 32) {
        // A tile 128x32, coalesced
#pragma unroll
        for (int p = 0; p < 16; p++) {
            int idx = tid + p * 256;
            int r = idx >> 5, c = idx & 31;
            int gr = rbase + r;
            float v = 0.f;
            if (gr < N) {
                v = A[(long)gr * K + k0 + c];
                if (BNIN) { int kc = k0 + c; v = fmaxf(fmaf(v, g_scale[kc], g_shift[kc]), 0.f); }
                if (BLEND) v = 0.5f * (v + A2[(long)gr * K + k0 + c]);
            }
            Ash[r][c] = v;
        }
        // W tile 32xFT
#pragma unroll
        for (int idx = tid; idx < 32 * FT; idx += 256) {
            int r = idx / FT, c = idx & (FT - 1);
            Wsh[r][c] = W[(long)(k0 + r) * F + cbase + c];
        }
        __syncthreads();

#pragma unroll 8
        for (int kk = 0; kk < 32; kk++) {
            u64 w[CP2];
            const ulonglong2* wp = reinterpret_cast<const ulonglong2*>(&Wsh[kk][c0]);
            {
                ulonglong2 t0 = wp[0];
                w[0] = t0.x; w[1] = t0.y;
                if (CP2 == 4) { ulonglong2 t1 = wp[1]; w[2] = t1.x; w[3] = t1.y; }
            }
#pragma unroll
            for (int i = 0; i < 4; i++) {
                float a = Ash[r0 + i][kk];
                u64 a2 = pack2(a, a);
#pragma unroll
                for (int j = 0; j < CP2; j++) fma2(acc[i][j], a2, w[j]);
            }
        }
        __syncthreads();
    }

    float av[4][CPT];
#pragma unroll
    for (int i = 0; i < 4; i++)
#pragma unroll
        for (int j = 0; j < CP2; j++) unpk2(acc[i][j], av[i][2 * j], av[i][2 * j + 1]);

    // add bias first (STATS are post-bias)
    if (bias) {
#pragma unroll
        for (int j = 0; j < CPT; j++) {
            float bj = bias[cbase + c0 + j];
#pragma unroll
            for (int i = 0; i < 4; i++) av[i][j] += bj;
        }
    }

    if (SD) {
        // per-row dots over the full 32-col row (FT==32). Lanes rg*8+cg:
        // reduce over cg within each 8-lane group via xor 1,2,4.
#pragma unroll
        for (int i = 0; i < 4; i++) {
            float sp = 0.f, dp = 0.f;
#pragma unroll
            for (int j = 0; j < CPT; j++) {
                float h = av[i][j];
                sp = fmaf(h, as_[c0 + j], sp);
                dp = fmaf(h, ad_[c0 + j], dp);
            }
#pragma unroll
            for (int o = 1; o < 8; o <<= 1) {
                sp += __shfl_xor_sync(0xffffffffu, sp, o);
                dp += __shfl_xor_sync(0xffffffffu, dp, o);
            }
            int gr = rbase + r0 + i;
            if (cg == 0 && gr < N) { g_s[gr] = sp; g_d[gr] = dp; }
        }
    }

    if (STATS) {
        // column partials: sum 4 rows (masking invalid), reduce across the
        // 4 row-groups in the warp (xor 8, 16), then one smem atomic per col.
#pragma unroll
        for (int j = 0; j < CPT; j++) {
            float sv = 0.f, sq = 0.f;
#pragma unroll
            for (int i = 0; i < 4; i++) {
                if (rbase + r0 + i < N) { float v = av[i][j]; sv += v; sq += v * v; }
            }
            sv += __shfl_xor_sync(0xffffffffu, sv, 8);
            sq += __shfl_xor_sync(0xffffffffu, sq, 8);
            sv += __shfl_xor_sync(0xffffffffu, sv, 16);
            sq += __shfl_xor_sync(0xffffffffu, sq, 16);
            if ((tid & 31) < 8) {
                atomicAdd(&s_sum[c0 + j], sv);
                atomicAdd(&s_sq[c0 + j], sq);
            }
        }
    }

    // store (vectorized float4)
#pragma unroll
    for (int i = 0; i < 4; i++) {
        int gr = rbase + r0 + i;
        if (gr < N) {
#pragma unroll
            for (int q = 0; q < CPT / 4; q++) {
                float4 v;
                v.x = av[i][q * 4 + 0]; v.y = av[i][q * 4 + 1];
                v.z = av[i][q * 4 + 2]; v.w = av[i][q * 4 + 3];
                if (RELU) {
                    v.x = fmaxf(v.x, 0.f); v.y = fmaxf(v.y, 0.f);
                    v.z = fmaxf(v.z, 0.f); v.w = fmaxf(v.w, 0.f);
                }
                *reinterpret_cast<float4*>(&C[(long)gr * F + cbase + c0 + q * 4]) = v;
            }
        }
    }

    if (STATS) {
        __syncthreads();
        if (tid < FT) {
            atomicAdd(&g_colsum[tid], s_sum[tid]);
            atomicAdd(&g_colsq[tid], s_sq[tid]);
        }
    }
}

// ---------------------------------------------------------------------------
// BatchNorm prep: scale/shift from accumulated stats; self-zeroes stats.
// ---------------------------------------------------------------------------
__global__ void bnprep_k(const float* __restrict__ g, const float* __restrict__ be, int Cc) {
    int c = threadIdx.x;
    float cs = (c < 64) ? g_colsum[c] : 0.f;
    float cq = (c < 64) ? g_colsq[c] : 0.f;
    if (c < Cc) {
        float invN = 1.0f / (float)NN;
        float m = cs * invN;
        float v = cq * invN - m * m;
        float sc = g[c] * rsqrtf(v + 1e-5f);
        g_scale[c] = sc;
        g_shift[c] = fmaf(-m, sc, be[c]);
    }
    if (c < 64) { g_colsum[c] = 0.f; g_colsq[c] = 0.f; }
}

// ---------------------------------------------------------------------------
// CSR build
// ---------------------------------------------------------------------------
__global__ void init_k() {
    int i = blockIdx.x * 256 + threadIdx.x;
    if (i < NN) g_deg[i] = 0;
}

__global__ __launch_bounds__(256) void hist_k(const int* __restrict__ ei) {
    int t = blockIdx.x * 256 + threadIdx.x;
    if (t >= TT) return;
    int dst = (t < NE) ? ei[NE + t] : (t - NE);
    atomicAdd(&g_deg[dst], 1);
}

__global__ __launch_bounds__(256) void scan1_k() {
    __shared__ int ws[9];
    int t = threadIdx.x, b = blockIdx.x;
    int i = b * 256 + t;
    int v = (i < NN) ? g_deg[i] : 0;
    int lane = t & 31, wid = t >> 5;
    int x = v;
#pragma unroll
    for (int o = 1; o < 32; o <<= 1) {
        int y = __shfl_up_sync(0xffffffffu, x, o);
        if (lane >= o) x += y;
    }
    if (lane == 31) ws[wid] = x;
    __syncthreads();
    if (t == 0) {
        int s = 0;
        for (int w = 0; w < 8; w++) { int tmp = ws[w]; ws[w] = s; s += tmp; }
        ws[8] = s;
    }
    __syncthreads();
    int excl = x - v + ws[wid];
    if (i < NN) g_rowoff[i] = excl;
    if (t == 0) g_partial[b] = ws[8];
}

__global__ __launch_bounds__(256) void scan2_k() {
    __shared__ int ws[9];
    int t = threadIdx.x;
    int v = (t < NPART) ? g_partial[t] : 0;
    int lane = t & 31, wid = t >> 5;
    int x = v;
#pragma unroll
    for (int o = 1; o < 32; o <<= 1) {
        int y = __shfl_up_sync(0xffffffffu, x, o);
        if (lane >= o) x += y;
    }
    if (lane == 31) ws[wid] = x;
    __syncthreads();
    if (t == 0) {
        int s = 0;
        for (int w = 0; w < 8; w++) { int tmp = ws[w]; ws[w] = s; s += tmp; }
        ws[8] = s;
    }
    __syncthreads();
    if (t < NPART) g_partial[t] = x - v + ws[wid];
}

__global__ void scan3_k() {
    int i = blockIdx.x * 256 + threadIdx.x;
    if (i < NN) {
        int off = g_rowoff[i] + g_partial[i >> 8];
        g_rowoff[i] = off;
        g_cursor[i] = off;
    }
}

__global__ __launch_bounds__(256) void scatter_k(const int* __restrict__ ei) {
    int t = blockIdx.x * 256 + threadIdx.x;
    if (t >= TT) return;
    int src, dst;
    if (t < NE) { src = ei[t]; dst = ei[NE + t]; }
    else        { src = dst = t - NE; }
    int p = atomicAdd(&g_cursor[dst], 1);
    g_csr[p] = src;
}

// ---------------------------------------------------------------------------
// GAT softmax-aggregate: warp per dst node, no atomics; exact-trip remainder.
// ---------------------------------------------------------------------------
__global__ __launch_bounds__(256) void agg_k(const float* __restrict__ Hg,
                                             const float* __restrict__ bias,
                                             float* __restrict__ outR) {
    int w = (blockIdx.x * 256 + threadIdx.x) >> 5;
    int lane = threadIdx.x & 31;
    if (w >= NN) return;
    int beg = g_rowoff[w];
    int n   = g_deg[w];
    float dd = g_d[w];
    float acc = 0.f, den = 0.f;
    int p0 = 0;
    for (; p0 + 32 <= n; p0 += 32) {
        int src = g_csr[beg + p0 + lane];
        float e = g_s[src] + dd;
        e = e > 0.f ? e : 0.2f * e;
        float ex = __expf(e);
#pragma unroll
        for (int j = 0; j < 32; j++) {
            float exj = __shfl_sync(0xffffffffu, ex, j);
            int   sj  = __shfl_sync(0xffffffffu, src, j);
            acc = fmaf(exj, Hg[sj * 32 + lane], acc);
            den += exj;
        }
    }
    int rem = n - p0;
    if (rem) {
        int src = 0; float ex = 0.f;
        if (lane < rem) {
            src = g_csr[beg + p0 + lane];
            float e = g_s[src] + dd;
            e = e > 0.f ? e : 0.2f * e;
            ex = __expf(e);
        }
        for (int j = 0; j < rem; j++) {
            float exj = __shfl_sync(0xffffffffu, ex, j);
            int   sj  = __shfl_sync(0xffffffffu, src, j);
            acc = fmaf(exj, Hg[sj * 32 + lane], acc);
            den += exj;
        }
    }
    outR[w * 32 + lane] = fmaxf(acc / den + bias[lane], 0.f);
}

// ---------------------------------------------------------------------------
// Orchestration: parallel branches (CSR ∥ MLP ∥ GAT-g1), joins for agg/final.
// ---------------------------------------------------------------------------
extern "C" void kernel_launch(void* const* d_in, const int* in_sizes, int n_in,
                              void* d_out, int out_size)
{
    const float* x     = (const float*)d_in[0];
    const int*   ei    = (const int*)  d_in[1];
    const float* W_g1  = (const float*)d_in[2];
    const float* as_g1 = (const float*)d_in[3];
    const float* ad_g1 = (const float*)d_in[4];
    const float* b_g1  = (const float*)d_in[5];
    const float* W_g2  = (const float*)d_in[6];
    const float* as_g2 = (const float*)d_in[7];
    const float* ad_g2 = (const float*)d_in[8];
    const float* b_g2  = (const float*)d_in[9];
    const float* W_gf  = (const float*)d_in[10];
    const float* b_gf  = (const float*)d_in[11];
    const float* W_m1  = (const float*)d_in[12];
    const float* b_m1  = (const float*)d_in[13];
    const float* g_m1  = (const float*)d_in[14];
    const float* be_m1 = (const float*)d_in[15];
    const float* W_m2  = (const float*)d_in[16];
    const float* b_m2  = (const float*)d_in[17];
    const float* g_m2  = (const float*)d_in[18];
    const float* be_m2 = (const float*)d_in[19];
    const float* W_m3  = (const float*)d_in[20];
    const float* b_m3  = (const float*)d_in[21];
    const float* g_m3  = (const float*)d_in[22];
    const float* be_m3 = (const float*)d_in[23];
    const float* W_f   = (const float*)d_in[24];
    const float* b_f   = (const float*)d_in[25];
    float* out = (float*)d_out;

    float *H1, *H2, *H3, *hg, *gh, *hf;
    cudaGetSymbolAddress((void**)&H1, g_H1);
    cudaGetSymbolAddress((void**)&H2, g_H2);
    cudaGetSymbolAddress((void**)&H3, g_H3);
    cudaGetSymbolAddress((void**)&hg, g_hg);
    cudaGetSymbolAddress((void**)&gh, g_gh);
    cudaGetSymbolAddress((void**)&hf, g_hf);

    const int GROWS = (NN + 127) / 128;   // 391
    const int EBLK  = (TT + 255) / 256;
    const int NBLK  = (NN + 255) / 256;
    const int ABLK  = (NN * 32 + 255) / 256;

    cudaStream_t s1 = g_ctx.s1, s2 = g_ctx.s2;
    cudaEventRecord(g_ctx.e0, 0);

    // ---- Branch 0: CSR build part 1 ----
    init_k<<<NBLK, 256>>>();
    hist_k<<<EBLK, 256>>>(ei);
    scan1_k<<<NPART, 256>>>();

    // ---- Branch 1 (s1): MLP chain ----
    cudaStreamWaitEvent(s1, g_ctx.e0, 0);
    gemm_k<64, false, false, false, true, false><<<dim3(GROWS, 1), 256, 0, s1>>>(
        x, nullptr, W_m1, b_m1, nullptr, nullptr, H1, NN, INCH, HID);   // profiled slot
    bnprep_k<<<1, 64, 0, s1>>>(g_m1, be_m1, 64);
    gemm_k<64, false, false, true, true, false><<<dim3(GROWS, 1), 256, 0, s1>>>(
        H1, nullptr, W_m2, b_m2, nullptr, nullptr, H2, NN, HID, HID);
    bnprep_k<<<1, 64, 0, s1>>>(g_m2, be_m2, 64);
    gemm_k<32, false, false, true, true, false><<<dim3(GROWS, 1), 256, 0, s1>>>(
        H2, nullptr, W_m3, b_m3, nullptr, nullptr, H3, NN, HID, LAT);
    bnprep_k<<<1, 64, 0, s1>>>(g_m3, be_m3, 32);
    cudaEventRecord(g_ctx.e1, s1);

    // ---- Branch 2 (s2): GAT layer-1 GEMM ----
    cudaStreamWaitEvent(s2, g_ctx.e0, 0);
    gemm_k<32, false, false, false, false, true><<<dim3(GROWS, 1), 256, 0, s2>>>(
        x, nullptr, W_g1, nullptr, as_g1, ad_g1, hg, NN, INCH, GATH);
    cudaEventRecord(g_ctx.e2, s2);

    // ---- Branch 0 continues: CSR build part 2 ----
    scan2_k<<<1, 256>>>();
    scan3_k<<<NBLK, 256>>>();
    scatter_k<<<EBLK, 256>>>(ei);

    // ---- Join GAT-g1; GAT chain ----
    cudaStreamWaitEvent(0, g_ctx.e2, 0);
    agg_k<<<ABLK, 256>>>(hg, b_g1, gh);
    gemm_k<32, false, false, false, false, true><<<dim3(GROWS, 1), 256>>>(
        gh, nullptr, W_g2, nullptr, as_g2, ad_g2, hg, NN, GATH, GATH);
    agg_k<<<ABLK, 256>>>(hg, b_g2, gh);
    gemm_k<32, false, false, false, false, false><<<dim3(GROWS, 1), 256>>>(
        gh, nullptr, W_gf, b_gf, nullptr, nullptr, hf, NN, GATH, LAT);

    // ---- Join MLP; final blended GEMM: out = relu((0.5*bnrelu(H3)+0.5*hf)@W_f + b_f) ----
    cudaStreamWaitEvent(0, g_ctx.e1, 0);
    gemm_k<64, true, true, true, false, false><<<dim3(GROWS, 4), 256>>>(
        H3, hf, W_f, b_f, nullptr, nullptr, out, NN, LAT, OUTC);
}

// round 6
// speedup vs baseline: 2.8053x; 1.0641x over previous
#include <cuda_runtime.h>

// Problem constants
#define NN   50000
#define NE   1600000
#define TT   (NE + NN)       // edges + self loops
#define INCH 256
#define HID  64
#define LAT  32
#define GATH 32
#define OUTC 256
#define NPART 196            // ceil(NN/256)

// ---------------------------------------------------------------------------
// Device scratch (static only)
// ---------------------------------------------------------------------------
__device__ __align__(128) float g_H1[NN * 64];
__device__ __align__(128) float g_H2[NN * 64];
__device__ __align__(128) float g_H3[NN * 32];
__device__ __align__(128) float g_hg[NN * 32];
__device__ __align__(128) float g_gh[NN * 32];
__device__ __align__(128) float g_hf[NN * 32];
__device__ __align__(128) float g_s[NN];
__device__ __align__(128) float g_d[NN];
__device__ __align__(128) int   g_deg[NN];
__device__ __align__(128) int   g_rowoff[NN];
__device__ __align__(128) int   g_cursor[NN];
__device__ __align__(128) int   g_csr[TT];
__device__ int   g_partial[256];
// zero at module load; bnprep_k re-zeroes after each use -> invariant holds.
__device__ float g_colsum[64], g_colsq[64];
__device__ float g_scale[64], g_shift[64];

// ---------------------------------------------------------------------------
// Streams/events created at module load (before harness mem checkpoints).
// ---------------------------------------------------------------------------
struct GpuCtx {
    cudaStream_t s1, s2;
    cudaEvent_t  e0, e1, e2;
    GpuCtx() {
        cudaStreamCreateWithFlags(&s1, cudaStreamNonBlocking);
        cudaStreamCreateWithFlags(&s2, cudaStreamNonBlocking);
        cudaEventCreateWithFlags(&e0, cudaEventDisableTiming);
        cudaEventCreateWithFlags(&e1, cudaEventDisableTiming);
        cudaEventCreateWithFlags(&e2, cudaEventDisableTiming);
    }
};
static GpuCtx g_ctx;

// ---------------------------------------------------------------------------
// f32x2 packed-FMA helpers (sm_103a FFMA2 — PTX only)
// ---------------------------------------------------------------------------
typedef unsigned long long u64;
__device__ __forceinline__ u64 pack2(float a, float b) {
    u64 r; asm("mov.b64 %0,{%1,%2};" : "=l"(r) : "f"(a), "f"(b)); return r;
}
__device__ __forceinline__ void fma2(u64& d, u64 a, u64 b) {
    asm("fma.rn.f32x2 %0, %1, %2, %0;" : "+l"(d) : "l"(a), "l"(b));
}
__device__ __forceinline__ void unpk2(u64 v, float& x, float& y) {
    asm("mov.b64 {%0,%1},%2;" : "=f"(x), "=f"(y) : "l"(v));
}

// ---------------------------------------------------------------------------
// Register-blocked fused GEMM:  C[N,F] = act(load(A)[N,K] @ W[K,F] + bias)
// Block tile: 128 rows x FT cols. THREADS = 16*(FT/4). Micro-tile: 8 rows x 4
// cols per thread, rows strided by 16 (rows rg+0,rg+16,...,rg+112).
// A tile in smem uses a 16B-chunk XOR swizzle (cc ^= r&7) so warp row groups
// (rows differ by 1) hit distinct banks with LDS.128 k-vector loads.
// Inner 4-k chunk: 8 A LDS.128 + 4 W LDS.128 -> 32 fma2.
// Flags: BNIN (bn+relu on A load), BLEND (0.5*(A+A2)), STATS (col sum/sq of
// C post-bias), SD (per-row dots vs as_/ad_ -> g_s/g_d; FT==32 only).
// ---------------------------------------------------------------------------
template<int FT, bool RELU, bool BLEND, bool BNIN, bool STATS, bool SD>
__global__ __launch_bounds__(16 * (FT / 4)) void gemm_k(
    const float* __restrict__ A, const float* __restrict__ A2,
    const float* __restrict__ W, const float* __restrict__ bias,
    const float* __restrict__ as_, const float* __restrict__ ad_,
    float* __restrict__ C, int N, int K, int F)
{
    constexpr int CG = FT / 4;            // col groups (8 or 16)
    constexpr int THREADS = 16 * CG;      // 128 or 256

    __shared__ __align__(16) float Ash[128][32];   // swizzled
    __shared__ __align__(16) float Wsh[32][FT];
    __shared__ float s_sum[FT], s_sq[FT];

    const int tid   = threadIdx.x;
    const int rbase = blockIdx.x * 128;
    const int cbase = blockIdx.y * FT;
    const int rg = tid / CG;              // 0..15
    const int cg = tid % CG;
    const int c0 = cg * 4;

    if (STATS && tid < FT) { s_sum[tid] = 0.f; s_sq[tid] = 0.f; }

    u64 acc[8][2];
#pragma unroll
    for (int i = 0; i < 8; i++) { acc[i][0] = 0ull; acc[i][1] = 0ull; }

    const int sw = rg & 7;                // per-thread A-chunk swizzle

    for (int k0 = 0; k0 < K; k0 += 32) {
        // ---- A tile 128x32 -> swizzled smem. Each warp-store covers 1+ rows,
        // within a row the swizzle is a permutation -> conflict-free.
#pragma unroll
        for (int p = 0; p < 4096 / THREADS; p++) {
            int idx = tid + p * THREADS;
            int r = idx >> 5, c = idx & 31;
            int gr = rbase + r;
            float v = 0.f;
            if (gr < N) {
                v = A[(long)gr * K + k0 + c];
                if (BNIN) { int kc = k0 + c; v = fmaxf(fmaf(v, g_scale[kc], g_shift[kc]), 0.f); }
                if (BLEND) v = 0.5f * (v + A2[(long)gr * K + k0 + c]);
            }
            int cc = (c >> 2) ^ (r & 7);
            Ash[r][cc * 4 + (c & 3)] = v;
        }
        // ---- W tile 32xFT
#pragma unroll
        for (int idx = tid; idx < 32 * FT; idx += THREADS) {
            int r = idx / FT, c = idx & (FT - 1);
            Wsh[r][c] = W[(long)(k0 + r) * F + cbase + c];
        }
        __syncthreads();

#pragma unroll
        for (int cc = 0; cc < 8; cc++) {
            // W vectors for the 4 k's of this chunk
            u64 w[4][2];
#pragma unroll
            for (int j = 0; j < 4; j++) {
                ulonglong2 t = *reinterpret_cast<const ulonglong2*>(&Wsh[cc * 4 + j][c0]);
                w[j][0] = t.x; w[j][1] = t.y;
            }
            int scc = (cc ^ sw) * 4;
            // A vectors: 8 rows, 4 k's each
            float4 a[8];
#pragma unroll
            for (int i = 0; i < 8; i++)
                a[i] = *reinterpret_cast<const float4*>(&Ash[rg + i * 16][scc]);
#pragma unroll
            for (int j = 0; j < 4; j++) {
#pragma unroll
                for (int i = 0; i < 8; i++) {
                    float as = (j == 0) ? a[i].x : (j == 1) ? a[i].y : (j == 2) ? a[i].z : a[i].w;
                    u64 a2 = pack2(as, as);
                    fma2(acc[i][0], a2, w[j][0]);
                    fma2(acc[i][1], a2, w[j][1]);
                }
            }
        }
        __syncthreads();
    }

    float av[8][4];
#pragma unroll
    for (int i = 0; i < 8; i++) {
        unpk2(acc[i][0], av[i][0], av[i][1]);
        unpk2(acc[i][1], av[i][2], av[i][3]);
    }

    // bias first (STATS are post-bias)
    if (bias) {
#pragma unroll
        for (int j = 0; j < 4; j++) {
            float bj = bias[cbase + c0 + j];
#pragma unroll
            for (int i = 0; i < 8; i++) av[i][j] += bj;
        }
    }

    if (SD) {
        // FT==32, CG==8: lanes with the same rg are 8 consecutive lanes.
#pragma unroll
        for (int i = 0; i < 8; i++) {
            float sp = 0.f, dp = 0.f;
#pragma unroll
            for (int j = 0; j < 4; j++) {
                float h = av[i][j];
                sp = fmaf(h, as_[c0 + j], sp);
                dp = fmaf(h, ad_[c0 + j], dp);
            }
#pragma unroll
            for (int o = 1; o < 8; o <<= 1) {
                sp += __shfl_xor_sync(0xffffffffu, sp, o);
                dp += __shfl_xor_sync(0xffffffffu, dp, o);
            }
            int gr = rbase + rg + i * 16;
            if (cg == 0 && gr < N) { g_s[gr] = sp; g_d[gr] = dp; }
        }
    }

    if (STATS) {
        // per-col partials over this thread's 8 rows, reduce across rg groups
        // within the warp (xor CG..16), then smem + global atomics.
#pragma unroll
        for (int j = 0; j < 4; j++) {
            float sv = 0.f, sq = 0.f;
#pragma unroll
            for (int i = 0; i < 8; i++) {
                if (rbase + rg + i * 16 < N) { float v = av[i][j]; sv += v; sq += v * v; }
            }
#pragma unroll
            for (int o = CG; o < 32; o <<= 1) {
                sv += __shfl_xor_sync(0xffffffffu, sv, o);
                sq += __shfl_xor_sync(0xffffffffu, sq, o);
            }
            if ((tid & 31) < CG) {
                atomicAdd(&s_sum[c0 + j], sv);
                atomicAdd(&s_sq[c0 + j], sq);
            }
        }
    }

    // store (float4 per row)
#pragma unroll
    for (int i = 0; i < 8; i++) {
        int gr = rbase + rg + i * 16;
        if (gr < N) {
            float4 v;
            v.x = av[i][0]; v.y = av[i][1]; v.z = av[i][2]; v.w = av[i][3];
            if (RELU) {
                v.x = fmaxf(v.x, 0.f); v.y = fmaxf(v.y, 0.f);
                v.z = fmaxf(v.z, 0.f); v.w = fmaxf(v.w, 0.f);
            }
            *reinterpret_cast<float4*>(&C[(long)gr * F + cbase + c0]) = v;
        }
    }

    if (STATS) {
        __syncthreads();
        if (tid < FT) {
            atomicAdd(&g_colsum[tid], s_sum[tid]);
            atomicAdd(&g_colsq[tid], s_sq[tid]);
        }
    }
}

// ---------------------------------------------------------------------------
// BatchNorm prep: scale/shift from accumulated stats; self-zeroes stats.
// ---------------------------------------------------------------------------
__global__ void bnprep_k(const float* __restrict__ g, const float* __restrict__ be, int Cc) {
    int c = threadIdx.x;
    float cs = (c < 64) ? g_colsum[c] : 0.f;
    float cq = (c < 64) ? g_colsq[c] : 0.f;
    if (c < Cc) {
        float invN = 1.0f / (float)NN;
        float m = cs * invN;
        float v = cq * invN - m * m;
        float sc = g[c] * rsqrtf(v + 1e-5f);
        g_scale[c] = sc;
        g_shift[c] = fmaf(-m, sc, be[c]);
    }
    if (c < 64) { g_colsum[c] = 0.f; g_colsq[c] = 0.f; }
}

// ---------------------------------------------------------------------------
// CSR build (vectorized edge passes: 4 edges per thread via int4)
// ---------------------------------------------------------------------------
__global__ void init_k() {
    int i = blockIdx.x * 256 + threadIdx.x;
    if (i < NN) g_deg[i] = 0;
}

__global__ __launch_bounds__(256) void hist_k(const int* __restrict__ ei) {
    int t = blockIdx.x * 256 + threadIdx.x;
    int q = NE / 4;
    if (t < q) {
        int4 d = reinterpret_cast<const int4*>(ei + NE)[t];
        atomicAdd(&g_deg[d.x], 1);
        atomicAdd(&g_deg[d.y], 1);
        atomicAdd(&g_deg[d.z], 1);
        atomicAdd(&g_deg[d.w], 1);
    } else {
        int i = t - q;
        if (i < NN) atomicAdd(&g_deg[i], 1);   // self loop
    }
}

__global__ __launch_bounds__(256) void scan1_k() {
    __shared__ int ws[9];
    int t = threadIdx.x, b = blockIdx.x;
    int i = b * 256 + t;
    int v = (i < NN) ? g_deg[i] : 0;
    int lane = t & 31, wid = t >> 5;
    int x = v;
#pragma unroll
    for (int o = 1; o < 32; o <<= 1) {
        int y = __shfl_up_sync(0xffffffffu, x, o);
        if (lane >= o) x += y;
    }
    if (lane == 31) ws[wid] = x;
    __syncthreads();
    if (t == 0) {
        int s = 0;
        for (int w = 0; w < 8; w++) { int tmp = ws[w]; ws[w] = s; s += tmp; }
        ws[8] = s;
    }
    __syncthreads();
    int excl = x - v + ws[wid];
    if (i < NN) g_rowoff[i] = excl;
    if (t == 0) g_partial[b] = ws[8];
}

__global__ __launch_bounds__(256) void scan2_k() {
    __shared__ int ws[9];
    int t = threadIdx.x;
    int v = (t < NPART) ? g_partial[t] : 0;
    int lane = t & 31, wid = t >> 5;
    int x = v;
#pragma unroll
    for (int o = 1; o < 32; o <<= 1) {
        int y = __shfl_up_sync(0xffffffffu, x, o);
        if (lane >= o) x += y;
    }
    if (lane == 31) ws[wid] = x;
    __syncthreads();
    if (t == 0) {
        int s = 0;
        for (int w = 0; w < 8; w++) { int tmp = ws[w]; ws[w] = s; s += tmp; }
        ws[8] = s;
    }
    __syncthreads();
    if (t < NPART) g_partial[t] = x - v + ws[wid];
}

__global__ void scan3_k() {
    int i = blockIdx.x * 256 + threadIdx.x;
    if (i < NN) {
        int off = g_rowoff[i] + g_partial[i >> 8];
        g_rowoff[i] = off;
        g_cursor[i] = off;
    }
}

__global__ __launch_bounds__(256) void scatter_k(const int* __restrict__ ei) {
    int t = blockIdx.x * 256 + threadIdx.x;
    int q = NE / 4;
    if (t < q) {
        int4 s = reinterpret_cast<const int4*>(ei)[t];
        int4 d = reinterpret_cast<const int4*>(ei + NE)[t];
        g_csr[atomicAdd(&g_cursor[d.x], 1)] = s.x;
        g_csr[atomicAdd(&g_cursor[d.y], 1)] = s.y;
        g_csr[atomicAdd(&g_cursor[d.z], 1)] = s.z;
        g_csr[atomicAdd(&g_cursor[d.w], 1)] = s.w;
    } else {
        int i = t - q;
        if (i < NN) g_csr[atomicAdd(&g_cursor[i], 1)] = i;   // self loop
    }
}

// ---------------------------------------------------------------------------
// GAT softmax-aggregate: warp per dst node, no atomics; exact-trip remainder.
// ---------------------------------------------------------------------------
__global__ __launch_bounds__(256) void agg_k(const float* __restrict__ Hg,
                                             const float* __restrict__ bias,
                                             float* __restrict__ outR) {
    int w = (blockIdx.x * 256 + threadIdx.x) >> 5;
    int lane = threadIdx.x & 31;
    if (w >= NN) return;
    int beg = g_rowoff[w];
    int n   = g_deg[w];
    float dd = g_d[w];
    float acc = 0.f, den = 0.f;
    int p0 = 0;
    for (; p0 + 32 <= n; p0 += 32) {
        int src = g_csr[beg + p0 + lane];
        float e = g_s[src] + dd;
        e = e > 0.f ? e : 0.2f * e;
        float ex = __expf(e);
#pragma unroll
        for (int j = 0; j < 32; j++) {
            float exj = __shfl_sync(0xffffffffu, ex, j);
            int   sj  = __shfl_sync(0xffffffffu, src, j);
            acc = fmaf(exj, Hg[sj * 32 + lane], acc);
            den += exj;
        }
    }
    int rem = n - p0;
    if (rem) {
        int src = 0; float ex = 0.f;
        if (lane < rem) {
            src = g_csr[beg + p0 + lane];
            float e = g_s[src] + dd;
            e = e > 0.f ? e : 0.2f * e;
            ex = __expf(e);
        }
        for (int j = 0; j < rem; j++) {
            float exj = __shfl_sync(0xffffffffu, ex, j);
            int   sj  = __shfl_sync(0xffffffffu, src, j);
            acc = fmaf(exj, Hg[sj * 32 + lane], acc);
            den += exj;
        }
    }
    outR[w * 32 + lane] = fmaxf(acc / den + bias[lane], 0.f);
}

// ---------------------------------------------------------------------------
// Orchestration: parallel branches (CSR ∥ MLP ∥ GAT-g1), joins for agg/final.
// ---------------------------------------------------------------------------
extern "C" void kernel_launch(void* const* d_in, const int* in_sizes, int n_in,
                              void* d_out, int out_size)
{
    const float* x     = (const float*)d_in[0];
    const int*   ei    = (const int*)  d_in[1];
    const float* W_g1  = (const float*)d_in[2];
    const float* as_g1 = (const float*)d_in[3];
    const float* ad_g1 = (const float*)d_in[4];
    const float* b_g1  = (const float*)d_in[5];
    const float* W_g2  = (const float*)d_in[6];
    const float* as_g2 = (const float*)d_in[7];
    const float* ad_g2 = (const float*)d_in[8];
    const float* b_g2  = (const float*)d_in[9];
    const float* W_gf  = (const float*)d_in[10];
    const float* b_gf  = (const float*)d_in[11];
    const float* W_m1  = (const float*)d_in[12];
    const float* b_m1  = (const float*)d_in[13];
    const float* g_m1  = (const float*)d_in[14];
    const float* be_m1 = (const float*)d_in[15];
    const float* W_m2  = (const float*)d_in[16];
    const float* b_m2  = (const float*)d_in[17];
    const float* g_m2  = (const float*)d_in[18];
    const float* be_m2 = (const float*)d_in[19];
    const float* W_m3  = (const float*)d_in[20];
    const float* b_m3  = (const float*)d_in[21];
    const float* g_m3  = (const float*)d_in[22];
    const float* be_m3 = (const float*)d_in[23];
    const float* W_f   = (const float*)d_in[24];
    const float* b_f   = (const float*)d_in[25];
    float* out = (float*)d_out;

    float *H1, *H2, *H3, *hg, *gh, *hf;
    cudaGetSymbolAddress((void**)&H1, g_H1);
    cudaGetSymbolAddress((void**)&H2, g_H2);
    cudaGetSymbolAddress((void**)&H3, g_H3);
    cudaGetSymbolAddress((void**)&hg, g_hg);
    cudaGetSymbolAddress((void**)&gh, g_gh);
    cudaGetSymbolAddress((void**)&hf, g_hf);

    const int GROWS = (NN + 127) / 128;                 // 391
    const int EBLK  = (NE / 4 + NN + 255) / 256;        // vectorized edge blocks
    const int NBLK  = (NN + 255) / 256;
    const int ABLK  = (NN * 32 + 255) / 256;

    cudaStream_t s1 = g_ctx.s1, s2 = g_ctx.s2;
    cudaEventRecord(g_ctx.e0, 0);

    // ---- Branch 0: CSR build part 1 ----
    init_k<<<NBLK, 256>>>();
    hist_k<<<EBLK, 256>>>(ei);
    scan1_k<<<NPART, 256>>>();

    // ---- Branch 1 (s1): MLP chain ----
    cudaStreamWaitEvent(s1, g_ctx.e0, 0);
    gemm_k<64, false, false, false, true, false><<<dim3(GROWS, 1), 256, 0, s1>>>(
        x, nullptr, W_m1, b_m1, nullptr, nullptr, H1, NN, INCH, HID);   // profiled slot
    bnprep_k<<<1, 64, 0, s1>>>(g_m1, be_m1, 64);
    gemm_k<64, false, false, true, true, false><<<dim3(GROWS, 1), 256, 0, s1>>>(
        H1, nullptr, W_m2, b_m2, nullptr, nullptr, H2, NN, HID, HID);
    bnprep_k<<<1, 64, 0, s1>>>(g_m2, be_m2, 64);
    gemm_k<32, false, false, true, true, false><<<dim3(GROWS, 1), 128, 0, s1>>>(
        H2, nullptr, W_m3, b_m3, nullptr, nullptr, H3, NN, HID, LAT);
    bnprep_k<<<1, 64, 0, s1>>>(g_m3, be_m3, 32);
    cudaEventRecord(g_ctx.e1, s1);

    // ---- Branch 2 (s2): GAT layer-1 GEMM ----
    cudaStreamWaitEvent(s2, g_ctx.e0, 0);
    gemm_k<32, false, false, false, false, true><<<dim3(GROWS, 1), 128, 0, s2>>>(
        x, nullptr, W_g1, nullptr, as_g1, ad_g1, hg, NN, INCH, GATH);
    cudaEventRecord(g_ctx.e2, s2);

    // ---- Branch 0 continues: CSR build part 2 ----
    scan2_k<<<1, 256>>>();
    scan3_k<<<NBLK, 256>>>();
    scatter_k<<<EBLK, 256>>>(ei);

    // ---- Join GAT-g1; GAT chain ----
    cudaStreamWaitEvent(0, g_ctx.e2, 0);
    agg_k<<<ABLK, 256>>>(hg, b_g1, gh);
    gemm_k<32, false, false, false, false, true><<<dim3(GROWS, 1), 128>>>(
        gh, nullptr, W_g2, nullptr, as_g2, ad_g2, hg, NN, GATH, GATH);
    agg_k<<<ABLK, 256>>>(hg, b_g2, gh);
    gemm_k<32, false, false, false, false, false><<<dim3(GROWS, 1), 128>>>(
        gh, nullptr, W_gf, b_gf, nullptr, nullptr, hf, NN, GATH, LAT);

    // ---- Join MLP; final blended GEMM ----
    cudaStreamWaitEvent(0, g_ctx.e1, 0);
    gemm_k<64, true, true, true, false, false><<<dim3(GROWS, 4), 256>>>(
        H3, hf, W_f, b_f, nullptr, nullptr, out, NN, LAT, OUTC);
}